// round 8
// baseline (speedup 1.0000x reference)
#include <cuda_runtime.h>
#include <cuda_fp16.h>

// ---------------------------------------------------------------------------
// GNNEncoder: 3x GCNConv(relu) -> sum -> global_mean_pool -> MLP
// R8: GEMM redesigned: 64x64 tile (higher occupancy), full-B smem preload,
// register double-buffer on layer-1 K-chunks (LDG overlaps MMA).
// ---------------------------------------------------------------------------

#define NMAX 50000
#define EMAX 800000
#define GMAX 2500
#define F 64
#define SCAN_B 1024
#define NBLK_MAX ((NMAX + SCAN_B - 1) / SCAN_B + 1)

__device__ int   g_cntpub[NMAX + NBLK_MAX];   // [0,N): cnt  [N,N+nblk): bpub
__device__ int   g_rowptr[NMAX + 1];
__device__ int   g_cursor[NMAX];
__device__ float g_dis[NMAX];
__device__ float g_dis2[NMAX];
__device__ int2  g_epack[EMAX];
__device__ __align__(16) __half g_h16[NMAX * F];     // GEMM output (gather target)
__device__ __align__(16) __half g_x1[NMAX * F];      // layer activations
__device__ __align__(16) __half g_x2[NMAX * F];
__device__ __align__(16) __half g_x3[NMAX * F];
__device__ __align__(16) __half g_w16t[3][64 * 128]; // W^T fp16, k-contig, stride 128

// ---------------- fused prep: cvtW x3 | hist ---------------------------------

__global__ void k_prep(const float* __restrict__ W1, const float* __restrict__ W2,
                       const float* __restrict__ W3,
                       const int* __restrict__ dst, int E) {
    int blk = blockIdx.x;
    if (blk < 64) {
        int i = blk * 256 + threadIdx.x;   // 0..16383
        const float* W; __half* Wt; int idx;
        if (i < 8192)       { W = W1; Wt = g_w16t[0]; idx = i; }
        else if (i < 12288) { W = W2; Wt = g_w16t[1]; idx = i - 8192; }
        else                { W = W3; Wt = g_w16t[2]; idx = i - 12288; }
        int k = idx >> 6, nn = idx & 63;
        Wt[nn * 128 + k] = __float2half(W[k * 64 + nn]);
        return;
    }
    blk -= 64;
    int e = blk * 256 + threadIdx.x;
    if (e < E) atomicAdd(&g_cntpub[dst[e]], 1);
}

// ---------------- single-pass decoupled scan (also dis/dis2) -----------------

__global__ void k_scan(int n, int nblk) {
    __shared__ int wsum[32];
    __shared__ int s_off;
    int i = blockIdx.x * SCAN_B + threadIdx.x;
    int lane = threadIdx.x & 31, wid = threadIdx.x >> 5;
    int v = (i < n) ? g_cntpub[i] : 0;
    if (i < n) {
        float deg = (float)(v + 1);
        g_dis[i]  = rsqrtf(deg);
        g_dis2[i] = 1.0f / deg;
    }
    int s = v;
#pragma unroll
    for (int o = 1; o < 32; o <<= 1) {
        int t = __shfl_up_sync(0xffffffffu, s, o);
        if (lane >= o) s += t;
    }
    if (lane == 31) wsum[wid] = s;
    __syncthreads();
    if (wid == 0) {
        int ws = wsum[lane];
#pragma unroll
        for (int o = 1; o < 32; o <<= 1) {
            int t = __shfl_up_sync(0xffffffffu, ws, o);
            if (lane >= o) ws += t;
        }
        wsum[lane] = ws;
    }
    __syncthreads();
    int incl = s + (wid > 0 ? wsum[wid - 1] : 0);
    int blk_total = wsum[31];
    volatile int* pub = (volatile int*)(g_cntpub + n);
    if (threadIdx.x == 0) pub[blockIdx.x] = blk_total + 1;
    if (wid == 0) {
        int off = 0;
        for (int j = lane; j < blockIdx.x; j += 32) {
            int pv;
            do { pv = pub[j]; } while (pv == 0);
            off += pv - 1;
        }
#pragma unroll
        for (int o = 16; o; o >>= 1) off += __shfl_xor_sync(0xffffffffu, off, o);
        if (lane == 0) s_off = off;
    }
    __syncthreads();
    int base = s_off;
    if (i < n) {
        int excl = base + incl - v;
        g_rowptr[i] = excl;
        g_cursor[i] = excl;
    }
    if (blockIdx.x == nblk - 1 && threadIdx.x == SCAN_B - 1)
        g_rowptr[n] = base + incl;
}

__global__ void k_fill(const int* __restrict__ src, const int* __restrict__ dst, int E) {
    int e = blockIdx.x * blockDim.x + threadIdx.x;
    if (e >= E) return;
    int s = src[e], d = dst[e];
    float nm = g_dis[s] * g_dis[d];
    int pos = atomicAdd(&g_cursor[d], 1);
    g_epack[pos] = make_int2(s, __float_as_int(nm));
}

// ---------------- tensor-core GEMM: H16[n,64] = A[n,K] @ W[K,64] -------------
// 64x64 tile, 8 warps (4m x 2n), m16n32 per warp. B preloaded in full.
// Layer 1 (K=128, fp32 in): register double-buffer across the 2 K-chunks,
// second chunk's LDGs issue before first chunk's MMAs (latency overlap).

#define APD 72   // As row pitch in halves

template<int K, bool F32>
__global__ void __launch_bounds__(256) k_gemm(const void* __restrict__ Ap,
                                              const __half* __restrict__ Wt,
                                              __half* __restrict__ H, int n) {
    constexpr int BPD = K + 8;
    __shared__ __half As[64 * APD];
    __shared__ __half Bs[64 * BPD];
    const float*  Af = (const float*)Ap;
    const __half* Ah = (const __half*)Ap;
    int row0 = blockIdx.x * 64;
    int tid = threadIdx.x, lane = tid & 31, warp = tid >> 5;
    int wm = (warp & 3) * 16, wn = (warp >> 2) * 32;
    int g = lane >> 2, t = lane & 3;
    float d[4][4] = {};

    // B: full [64, K] preload (Wt row pitch 128)
#pragma unroll
    for (int it = 0; it < K / 32; it++) {
        int idx = tid + it * 256;
        int r = idx / (K / 8), seg = (idx % (K / 8)) * 8;
        *(uint4*)(Bs + r * BPD + seg) = *(const uint4*)(Wt + (size_t)r * 128 + seg);
    }

    // compute one 64-col K-chunk from As against Bs[:, kbase:kbase+64]
    auto compute = [&](int kbase) {
#pragma unroll
        for (int kk = 0; kk < 4; kk++) {
            unsigned a[4], b[4][2];
            const __half* ap = As + (wm + g) * APD + kk * 16 + t * 2;
            a[0] = *(const unsigned*)ap;
            a[1] = *(const unsigned*)(ap + 8 * APD);
            a[2] = *(const unsigned*)(ap + 8);
            a[3] = *(const unsigned*)(ap + 8 * APD + 8);
#pragma unroll
            for (int j = 0; j < 4; j++) {
                const __half* bp = Bs + (wn + j * 8 + g) * BPD + kbase + kk * 16 + t * 2;
                b[j][0] = *(const unsigned*)bp;
                b[j][1] = *(const unsigned*)(bp + 8);
            }
#pragma unroll
            for (int j = 0; j < 4; j++)
                asm volatile(
                    "mma.sync.aligned.m16n8k16.row.col.f32.f16.f16.f32 "
                    "{%0,%1,%2,%3}, {%4,%5,%6,%7}, {%8,%9}, {%0,%1,%2,%3};"
                    : "+f"(d[j][0]), "+f"(d[j][1]), "+f"(d[j][2]), "+f"(d[j][3])
                    : "r"(a[0]), "r"(a[1]), "r"(a[2]), "r"(a[3]),
                      "r"(b[j][0]), "r"(b[j][1]));
        }
    };

    if constexpr (F32) {
        // 64 rows x 64 fp32 per chunk -> 1024 float4, 4 per thread
        float4 fa[4];
        auto loadA = [&](int kb) {
#pragma unroll
            for (int it = 0; it < 4; it++) {
                int idx = tid + it * 256;
                int r = idx >> 4, c = (idx & 15) * 4;
                fa[it] = (row0 + r < n)
                       ? *(const float4*)(Af + (size_t)(row0 + r) * K + kb + c)
                       : make_float4(0.f, 0.f, 0.f, 0.f);
            }
        };
        auto storeA = [&]() {
#pragma unroll
            for (int it = 0; it < 4; it++) {
                int idx = tid + it * 256;
                int r = idx >> 4, c = (idx & 15) * 4;
                __half2 h0 = __floats2half2_rn(fa[it].x, fa[it].y);
                __half2 h1 = __floats2half2_rn(fa[it].z, fa[it].w);
                uint2 u;
                u.x = *(unsigned*)&h0; u.y = *(unsigned*)&h1;
                *(uint2*)(As + r * APD + c) = u;
            }
        };
        loadA(0);
        storeA();
        __syncthreads();
        loadA(64);        // LDGs in flight during chunk-0 compute
        compute(0);
        __syncthreads();  // all reads of As done
        storeA();
        __syncthreads();
        compute(64);
    } else {
        // fp16 A: 64x64 halves = 512 uint4, 2 per thread
#pragma unroll
        for (int it = 0; it < 2; it++) {
            int idx = tid + it * 256;
            int r = idx >> 3, seg = (idx & 7) * 8;
            uint4 v = make_uint4(0u, 0u, 0u, 0u);
            if (row0 + r < n)
                v = *(const uint4*)(Ah + (size_t)(row0 + r) * K + seg);
            *(uint4*)(As + r * APD + seg) = v;
        }
        __syncthreads();
        compute(0);
    }

    int r0 = row0 + wm + g;
#pragma unroll
    for (int j = 0; j < 4; j++) {
        int c = wn + j * 8 + t * 2;
        __half2 lo = __floats2half2_rn(d[j][0], d[j][1]);
        __half2 hi = __floats2half2_rn(d[j][2], d[j][3]);
        if (r0 < n)     *(__half2*)(H + (size_t)r0 * F + c) = lo;
        if (r0 + 8 < n) *(__half2*)(H + (size_t)(r0 + 8) * F + c) = hi;
    }
}

// ---------------- CSR aggregate: warp per dst, quarter-warp per edge --------

__device__ __forceinline__ void fma8(float* acc, uint4 u, float nm) {
    __half2* hp = (__half2*)&u;
    float2 f0 = __half22float2(hp[0]);
    float2 f1 = __half22float2(hp[1]);
    float2 f2 = __half22float2(hp[2]);
    float2 f3 = __half22float2(hp[3]);
    acc[0] += nm * f0.x; acc[1] += nm * f0.y;
    acc[2] += nm * f1.x; acc[3] += nm * f1.y;
    acc[4] += nm * f2.x; acc[5] += nm * f2.y;
    acc[6] += nm * f3.x; acc[7] += nm * f3.y;
}

__global__ void k_agg(const __half* __restrict__ h, const float* __restrict__ b,
                      __half* __restrict__ xout, int n) {
    int w = (blockIdx.x * blockDim.x + threadIdx.x) >> 5;
    int lane = threadIdx.x & 31;
    if (w >= n) return;
    int qid = lane >> 3;
    int ql  = lane & 7;

    int beg = g_rowptr[w], end = g_rowptr[w + 1];
    float self = g_dis2[w];
    uint4 selfu = __ldg((const uint4*)(h + (size_t)w * F) + ql);

    float acc[8] = {};
    int k = beg;

    for (; k + 16 <= end; k += 16) {
        int2 e0 = g_epack[k + qid];
        int2 e1 = g_epack[k + 4 + qid];
        int2 e2 = g_epack[k + 8 + qid];
        int2 e3 = g_epack[k + 12 + qid];
        uint4 v0 = __ldg((const uint4*)(h + (size_t)e0.x * F) + ql);
        uint4 v1 = __ldg((const uint4*)(h + (size_t)e1.x * F) + ql);
        uint4 v2 = __ldg((const uint4*)(h + (size_t)e2.x * F) + ql);
        uint4 v3 = __ldg((const uint4*)(h + (size_t)e3.x * F) + ql);
        fma8(acc, v0, __int_as_float(e0.y));
        fma8(acc, v1, __int_as_float(e1.y));
        fma8(acc, v2, __int_as_float(e2.y));
        fma8(acc, v3, __int_as_float(e3.y));
    }
    if (k + 8 <= end) {
        int2 e0 = g_epack[k + qid];
        int2 e1 = g_epack[k + 4 + qid];
        uint4 v0 = __ldg((const uint4*)(h + (size_t)e0.x * F) + ql);
        uint4 v1 = __ldg((const uint4*)(h + (size_t)e1.x * F) + ql);
        fma8(acc, v0, __int_as_float(e0.y));
        fma8(acc, v1, __int_as_float(e1.y));
        k += 8;
    }
    if (k + 4 <= end) {
        int2 e0 = g_epack[k + qid];
        uint4 v0 = __ldg((const uint4*)(h + (size_t)e0.x * F) + ql);
        fma8(acc, v0, __int_as_float(e0.y));
        k += 4;
    }
    if (k + qid < end) {
        int2 e0 = g_epack[k + qid];
        uint4 v0 = __ldg((const uint4*)(h + (size_t)e0.x * F) + ql);
        fma8(acc, v0, __int_as_float(e0.y));
    }
#pragma unroll
    for (int j = 0; j < 8; j++) {
        acc[j] += __shfl_xor_sync(0xffffffffu, acc[j], 8);
        acc[j] += __shfl_xor_sync(0xffffffffu, acc[j], 16);
    }

    fma8(acc, selfu, self);   // self loop

    if (qid == 0) {
        float4 bv0 = __ldg((const float4*)b + ql * 2);
        float4 bv1 = __ldg((const float4*)b + ql * 2 + 1);
        __half2 q0 = __floats2half2_rn(fmaxf(acc[0] + bv0.x, 0.f), fmaxf(acc[1] + bv0.y, 0.f));
        __half2 q1 = __floats2half2_rn(fmaxf(acc[2] + bv0.z, 0.f), fmaxf(acc[3] + bv0.w, 0.f));
        __half2 q2 = __floats2half2_rn(fmaxf(acc[4] + bv1.x, 0.f), fmaxf(acc[5] + bv1.y, 0.f));
        __half2 q3 = __floats2half2_rn(fmaxf(acc[6] + bv1.z, 0.f), fmaxf(acc[7] + bv1.w, 0.f));
        uint4 u;
        u.x = *(unsigned*)&q0; u.y = *(unsigned*)&q1;
        u.z = *(unsigned*)&q2; u.w = *(unsigned*)&q3;
        *(uint4*)(xout + (size_t)w * F + ql * 8) = u;
    }
}

// ---------------- fused pool + MLP (sums x1+x2+x3) ----------------------------

__device__ __forceinline__ int lower_bound_i(const int* __restrict__ a, int n, int key) {
    int lo = 0, hi = n;
    while (lo < hi) {
        int mid = (lo + hi) >> 1;
        if (a[mid] < key) lo = mid + 1; else hi = mid;
    }
    return lo;
}

__global__ void k_poolmlp(const int* __restrict__ batch, int n,
                          const float* __restrict__ Wp1, const float* __restrict__ bp1,
                          const float* __restrict__ Wp2, const float* __restrict__ bp2,
                          float* __restrict__ out) {
    __shared__ int s_range[2];
    __shared__ float p[F], t1[F];
    int g = blockIdx.x, j = threadIdx.x;
    if (j < 2) s_range[j] = lower_bound_i(batch, n, g + j);
    __syncthreads();
    int st = s_range[0], en = s_range[1];
    float acc = 0.f;
    for (int node = st; node < en; node++) {
        size_t o = (size_t)node * F + j;
        acc += __half2float(g_x1[o]) + __half2float(g_x2[o]) + __half2float(g_x3[o]);
    }
    float inv = 1.0f / fmaxf((float)(en - st), 1.0f);
    p[j] = acc * inv;
    __syncthreads();
    float a = bp1[j];
#pragma unroll
    for (int k = 0; k < F; k++) a += p[k] * Wp1[k * F + j];
    t1[j] = fmaxf(a, 0.f);
    __syncthreads();
    if (j < 32) {
        float a2 = bp2[j];
#pragma unroll
        for (int k = 0; k < F; k++) a2 += t1[k] * Wp2[k * 32 + j];
        out[g * 32 + j] = a2;
    }
}

// ---------------- launch -----------------------------------------------------

extern "C" void kernel_launch(void* const* d_in, const int* in_sizes, int n_in,
                              void* d_out, int out_size) {
    const float* x    = (const float*)d_in[0];
    const int*   ei   = (const int*)d_in[1];
    const int*   batch= (const int*)d_in[2];
    const float* W1   = (const float*)d_in[3];
    const float* b1   = (const float*)d_in[4];
    const float* W2   = (const float*)d_in[5];
    const float* b2   = (const float*)d_in[6];
    const float* W3   = (const float*)d_in[7];
    const float* b3   = (const float*)d_in[8];
    const float* Wp1  = (const float*)d_in[9];
    const float* bp1  = (const float*)d_in[10];
    const float* Wp2  = (const float*)d_in[11];
    const float* bp2  = (const float*)d_in[12];
    float* out = (float*)d_out;

    int N = in_sizes[0] / 128;
    int E = in_sizes[1] / 2;
    int G = out_size / 32;
    const int* src = ei;
    const int* dst = ei + E;

    __half *p_h, *p_x1, *p_x2, *p_x3, *p_wt;
    int *p_cnt;
    cudaGetSymbolAddress((void**)&p_h, g_h16);
    cudaGetSymbolAddress((void**)&p_x1, g_x1);
    cudaGetSymbolAddress((void**)&p_x2, g_x2);
    cudaGetSymbolAddress((void**)&p_x3, g_x3);
    cudaGetSymbolAddress((void**)&p_wt, g_w16t);
    cudaGetSymbolAddress((void**)&p_cnt, g_cntpub);

    __half* wt1 = p_wt;
    __half* wt2 = p_wt + 64 * 128;
    __half* wt3 = p_wt + 2 * 64 * 128;

    const int T = 256;
    int nblk = (N + SCAN_B - 1) / SCAN_B;

    cudaMemsetAsync(p_cnt, 0, ((size_t)N + nblk) * sizeof(int));

    int nH = (E + T - 1) / T;
    k_prep<<<64 + nH, T>>>(W1, W2, W3, dst, E);
    k_scan<<<nblk, SCAN_B>>>(N, nblk);
    k_fill<<<(E + T - 1) / T, T>>>(src, dst, E);

    int gemm_blocks = (N + 63) / 64;
    int agg_blocks  = (N + 7) / 8;

    // layer 1 (fp32 input, conversion fused into tile load, reg double-buffer)
    k_gemm<128, true><<<gemm_blocks, T>>>(x, wt1, p_h, N);
    k_agg<<<agg_blocks, T>>>(p_h, b1, p_x1, N);
    // layer 2
    k_gemm<64, false><<<gemm_blocks, T>>>(p_x1, wt2, p_h, N);
    k_agg<<<agg_blocks, T>>>(p_h, b2, p_x2, N);
    // layer 3
    k_gemm<64, false><<<gemm_blocks, T>>>(p_x2, wt3, p_h, N);
    k_agg<<<agg_blocks, T>>>(p_h, b3, p_x3, N);

    // fused pooling + MLP
    k_poolmlp<<<G, F>>>(batch, N, Wp1, bp1, Wp2, bp2, out);
}